// round 1
// baseline (speedup 1.0000x reference)
#include <cuda_runtime.h>

#define NNODES 50000
#define NEDGE  800000
#define ETOT   850000
#define DIM    128
#define NH     4
#define NB     7
#define KDIM   1024   // DIM * (1 + NB)
#define NGR    64
#define NCLS   10
#define NLAYER 3

// ---------------- device scratch (static: no runtime allocation) ----------------
__device__ __align__(16) float g_F[(size_t)NNODES * KDIM];   // 204.8 MB features
__device__ __align__(16) float g_W[KDIM * DIM];              // packed per-layer weight
__device__ __align__(16) float g_h[NNODES * DIM];            // layer input (post-silu)
__device__ __align__(16) float g_hl[NNODES * DIM];           // kan_linear output
__device__ __align__(16) float g_acc[NNODES * DIM];          // message accumulator
__device__ __align__(16) float g_asrc[NNODES * NH];
__device__ __align__(16) float g_adst[NNODES * NH];
__device__ __align__(16) float g_ex[(size_t)ETOT * NH];
__device__ __align__(16) float g_segsum[NNODES * NH];
__device__ __align__(16) float g_pooled[NGR * DIM];

// ---------------- helpers ----------------
__device__ __forceinline__ float silu_f(float x) {
    return x / (1.0f + __expf(-x));
}

// Cubic B-splines on uniform grid g[t] = 0.5*t - 2.5, t=0..10  (GS=4, K=3 -> 7 bases)
__device__ __forceinline__ void bsplines7(float x, float* out) {
    float b0[10];
#pragma unroll
    for (int i = 0; i < 10; i++) {
        float g0 = 0.5f * (float)i - 2.5f;
        b0[i] = (x >= g0 && x < g0 + 0.5f) ? 1.0f : 0.0f;
    }
    float b1[9];
#pragma unroll
    for (int i = 0; i < 9; i++) {
        float gi = 0.5f * (float)i - 2.5f;
        b1[i] = (x - gi) * 2.0f * b0[i] + ((gi + 1.0f) - x) * 2.0f * b0[i + 1];
    }
    float b2[8];
#pragma unroll
    for (int i = 0; i < 8; i++) {
        float gi = 0.5f * (float)i - 2.5f;
        b2[i] = (x - gi) * b1[i] + ((gi + 1.5f) - x) * b1[i + 1];
    }
#pragma unroll
    for (int i = 0; i < 7; i++) {
        float gi = 0.5f * (float)i - 2.5f;
        out[i] = ((x - gi) * b2[i] + ((gi + 2.0f) - x) * b2[i + 1]) * (1.0f / 1.5f);
    }
}

// Vector f32 reduction (sm_90+): 4 floats per op instead of 4 scalar atomics
__device__ __forceinline__ void red_add_v4(float* addr, float4 v) {
    asm volatile("red.global.add.v4.f32 [%0], {%1, %2, %3, %4};"
                 :: "l"(addr), "f"(v.x), "f"(v.y), "f"(v.z), "f"(v.w) : "memory");
}

// ---------------- kernels ----------------

// Pack [1024 x 128] combined weight: rows 0..127 = base_w^T, rows 128+j*7+b = spline_w*scaler
__global__ void pack_w_kernel(const float* __restrict__ bw,
                              const float* __restrict__ sw,
                              const float* __restrict__ sc) {
    int idx = blockIdx.x * blockDim.x + threadIdx.x;   // KDIM*DIM = 131072
    if (idx >= KDIM * DIM) return;
    int k = idx >> 7, o = idx & 127;
    float v;
    if (k < DIM) {
        v = bw[o * DIM + k];
    } else {
        int j = (k - DIM) / 7, b = (k - DIM) % 7;
        v = sw[o * DIM * NB + j * NB + b] * sc[o * DIM + j];
    }
    g_W[idx] = v;
}

// Build F[n, 0:128]=silu(x), F[n, 128+i*7+b]=basis
__global__ void feat_kernel(const float* __restrict__ in) {
    int idx = blockIdx.x * blockDim.x + threadIdx.x;
    if (idx >= NNODES * DIM) return;
    int n = idx >> 7, i = idx & 127;
    float x = in[idx];
    float* Fr = &g_F[(size_t)n * KDIM];
    Fr[i] = silu_f(x);
    float bs[7];
    bsplines7(x, bs);
#pragma unroll
    for (int b = 0; b < 7; b++) Fr[DIM + i * 7 + b] = bs[b];
}

// C[N,128] = F[N,1024] @ W[1024,128]; 128x128 tile, BK=16, 8x8 per thread
__global__ void __launch_bounds__(256) sgemm_kernel() {
    __shared__ float As[16][128];
    __shared__ float Bs[16][128];
    int tid = threadIdx.x;
    int m0 = blockIdx.x * 128;
    float acc[8][8];
#pragma unroll
    for (int i = 0; i < 8; i++)
#pragma unroll
        for (int j = 0; j < 8; j++) acc[i][j] = 0.0f;

    int ty = tid >> 4, tx = tid & 15;
    int ar = tid >> 2, ac = (tid & 3) << 2;       // A tile: 128 rows x 16 cols
    int br = tid >> 5, bc = (tid & 31) << 2;      // B tile: 16 rows x 128 cols

    for (int k0 = 0; k0 < KDIM; k0 += 16) {
#pragma unroll
        for (int r = 0; r < 2; r++) {
            int row = ar + r * 64;
            float4 v = make_float4(0.f, 0.f, 0.f, 0.f);
            if (m0 + row < NNODES)
                v = *(const float4*)&g_F[(size_t)(m0 + row) * KDIM + k0 + ac];
            As[ac + 0][row] = v.x;
            As[ac + 1][row] = v.y;
            As[ac + 2][row] = v.z;
            As[ac + 3][row] = v.w;
        }
#pragma unroll
        for (int r = 0; r < 2; r++) {
            int rowb = br + r * 8;
            *(float4*)&Bs[rowb][bc] = *(const float4*)&g_W[(k0 + rowb) * DIM + bc];
        }
        __syncthreads();
#pragma unroll
        for (int k = 0; k < 16; k++) {
            float ra[8], rb[8];
            *(float4*)&ra[0] = *(const float4*)&As[k][ty * 8];
            *(float4*)&ra[4] = *(const float4*)&As[k][ty * 8 + 4];
            *(float4*)&rb[0] = *(const float4*)&Bs[k][tx * 8];
            *(float4*)&rb[4] = *(const float4*)&Bs[k][tx * 8 + 4];
#pragma unroll
            for (int i = 0; i < 8; i++)
#pragma unroll
                for (int j = 0; j < 8; j++)
                    acc[i][j] += ra[i] * rb[j];
        }
        __syncthreads();
    }
#pragma unroll
    for (int i = 0; i < 8; i++) {
        int row = m0 + ty * 8 + i;
        if (row < NNODES) {
            *(float4*)&g_hl[(size_t)row * DIM + tx * 8] =
                make_float4(acc[i][0], acc[i][1], acc[i][2], acc[i][3]);
            *(float4*)&g_hl[(size_t)row * DIM + tx * 8 + 4] =
                make_float4(acc[i][4], acc[i][5], acc[i][6], acc[i][7]);
        }
    }
}

// a_src[n,h] = sum_c h[n,h,c]*att_src[h,c]; one warp per node
__global__ void att_prep_kernel(const float* __restrict__ attS,
                                const float* __restrict__ attD) {
    int gid = blockIdx.x * blockDim.x + threadIdx.x;
    int n = gid >> 5, lane = gid & 31;
    if (n >= NNODES) return;
    float4 v  = *(const float4*)&g_hl[(size_t)n * DIM + lane * 4];
    float4 ws = *(const float4*)&attS[lane * 4];
    float4 wd = *(const float4*)&attD[lane * 4];
    float ss = v.x * ws.x + v.y * ws.y + v.z * ws.z + v.w * ws.w;
    float sd = v.x * wd.x + v.y * wd.y + v.z * wd.z + v.w * wd.w;
#pragma unroll
    for (int o = 1; o <= 4; o <<= 1) {
        ss += __shfl_xor_sync(0xffffffffu, ss, o);
        sd += __shfl_xor_sync(0xffffffffu, sd, o);
    }
    if ((lane & 7) == 0) {
        int hh = lane >> 3;
        g_asrc[n * 4 + hh] = ss;
        g_adst[n * 4 + hh] = sd;
    }
}

// acc = bias (broadcast), segsum = 0
__global__ void init_layer_kernel(const float* __restrict__ bias) {
    int i = blockIdx.x * blockDim.x + threadIdx.x;
    if (i < NNODES * DIM) g_acc[i] = bias[i & 127];
    if (i < NNODES * NH) g_segsum[i] = 0.0f;
}

// Edge pass 1: ex = exp(leaky_relu(a_src[s]+a_dst[d])), segsum[d] += ex
__global__ void edge_a_kernel(const int* __restrict__ ei) {
    int e = blockIdx.x * blockDim.x + threadIdx.x;
    if (e >= ETOT) return;
    int s, d;
    if (e < NEDGE) { s = __ldg(&ei[e]); d = __ldg(&ei[NEDGE + e]); }
    else           { s = e - NEDGE; d = s; }
    float4 va = *(const float4*)&g_asrc[s * 4];
    float4 vb = *(const float4*)&g_adst[d * 4];
    float4 v;
    v.x = va.x + vb.x; v.y = va.y + vb.y; v.z = va.z + vb.z; v.w = va.w + vb.w;
    v.x = v.x > 0.f ? v.x : 0.2f * v.x;
    v.y = v.y > 0.f ? v.y : 0.2f * v.y;
    v.z = v.z > 0.f ? v.z : 0.2f * v.z;
    v.w = v.w > 0.f ? v.w : 0.2f * v.w;
    v.x = __expf(v.x); v.y = __expf(v.y); v.z = __expf(v.z); v.w = __expf(v.w);
    *(float4*)&g_ex[(size_t)e * 4] = v;
    red_add_v4(&g_segsum[d * 4], v);
}

// Edge pass 2: acc[d] += alpha * h[s]; one warp per edge (32 lanes x float4 = 128)
__global__ void edge_b_kernel(const int* __restrict__ ei) {
    int gid = blockIdx.x * blockDim.x + threadIdx.x;
    int e = gid >> 5;
    int lane = gid & 31;
    if (e >= ETOT) return;
    int s, d;
    if (e < NEDGE) { s = __ldg(&ei[e]); d = __ldg(&ei[NEDGE + e]); }
    else           { s = e - NEDGE; d = s; }
    int hh = lane >> 3;
    float alpha = g_ex[(size_t)e * 4 + hh] / (g_segsum[d * 4 + hh] + 1e-16f);
    float4 v = *(const float4*)&g_hl[(size_t)s * DIM + lane * 4];
    v.x *= alpha; v.y *= alpha; v.z *= alpha; v.w *= alpha;
    red_add_v4(&g_acc[(size_t)d * DIM + lane * 4], v);
}

__global__ void silu_kernel() {
    int i = blockIdx.x * blockDim.x + threadIdx.x;
    if (i < NNODES * DIM) {
        float v = g_acc[i];
        g_h[i] = silu_f(v);
    }
}

__global__ void zero_pooled_kernel() {
    int i = blockIdx.x * blockDim.x + threadIdx.x;
    if (i < NGR * DIM) g_pooled[i] = 0.0f;
}

// batch is sorted: running sum per column, flush on graph change
__global__ void pool_kernel(const int* __restrict__ batch) {
    int d0 = threadIdx.x;                 // 128 threads
    int r0 = blockIdx.x * 512;
    if (r0 >= NNODES) return;
    int rend = min(r0 + 512, NNODES);
    int cur = __ldg(&batch[r0]);
    float sum = 0.0f;
    for (int n = r0; n < rend; n++) {
        int g = __ldg(&batch[n]);
        if (g != cur) {
            atomicAdd(&g_pooled[cur * DIM + d0], sum);
            sum = 0.0f;
            cur = g;
        }
        sum += g_h[(size_t)n * DIM + d0];
    }
    atomicAdd(&g_pooled[cur * DIM + d0], sum);
}

// Readout KANLinear [128->10] + log_softmax. One block per graph, 128 threads.
__global__ void readout_kernel(const float* __restrict__ bw,
                               const float* __restrict__ sw,
                               const float* __restrict__ sc,
                               float* __restrict__ out) {
    __shared__ float feat[KDIM];
    __shared__ float sred[NCLS * 4];
    int g = blockIdx.x, t = threadIdx.x;
    float xv = g_pooled[g * DIM + t];
    feat[t] = xv / (1.0f + expf(-xv));
    float bs[7];
    bsplines7(xv, bs);
#pragma unroll
    for (int b = 0; b < 7; b++) feat[DIM + t * 7 + b] = bs[b];
    __syncthreads();

    float accv[NCLS];
#pragma unroll
    for (int o = 0; o < NCLS; o++) accv[o] = 0.0f;
#pragma unroll
    for (int kk = 0; kk < 8; kk++) {
        int k = kk * DIM + t;
        float f = feat[k];
        if (k < DIM) {
#pragma unroll
            for (int o = 0; o < NCLS; o++) accv[o] += f * bw[o * DIM + k];
        } else {
            int j = (k - DIM) / 7, b = (k - DIM) % 7;
#pragma unroll
            for (int o = 0; o < NCLS; o++)
                accv[o] += f * sw[o * DIM * NB + j * NB + b] * sc[o * DIM + j];
        }
    }
    int lane = t & 31, warp = t >> 5;
#pragma unroll
    for (int o = 0; o < NCLS; o++) {
        float v = accv[o];
#pragma unroll
        for (int off = 16; off >= 1; off >>= 1) v += __shfl_xor_sync(0xffffffffu, v, off);
        if (lane == 0) sred[o * 4 + warp] = v;
    }
    __syncthreads();
    if (t == 0) {
        float lg[NCLS];
        float mx = -1e30f;
#pragma unroll
        for (int o = 0; o < NCLS; o++) {
            lg[o] = sred[o * 4] + sred[o * 4 + 1] + sred[o * 4 + 2] + sred[o * 4 + 3];
            mx = fmaxf(mx, lg[o]);
        }
        float se = 0.0f;
#pragma unroll
        for (int o = 0; o < NCLS; o++) se += expf(lg[o] - mx);
        float lse = logf(se) + mx;
#pragma unroll
        for (int o = 0; o < NCLS; o++) out[g * NCLS + o] = lg[o] - lse;
    }
}

// ---------------- launch ----------------
extern "C" void kernel_launch(void* const* d_in, const int* in_sizes, int n_in,
                              void* d_out, int out_size) {
    const float* x        = (const float*)d_in[0];
    const int*   ei       = (const int*)d_in[1];
    const int*   batch    = (const int*)d_in[2];
    const float* base_w   = (const float*)d_in[3];
    const float* spline_w = (const float*)d_in[4];
    const float* scaler   = (const float*)d_in[5];
    const float* att_src  = (const float*)d_in[6];
    const float* att_dst  = (const float*)d_in[7];
    const float* bias     = (const float*)d_in[8];
    const float* ro_bw    = (const float*)d_in[9];
    const float* ro_sw    = (const float*)d_in[10];
    const float* ro_sc    = (const float*)d_in[11];
    float* out = (float*)d_out;

    float* hbuf = nullptr;
    cudaGetSymbolAddress((void**)&hbuf, g_h);

    const int ND_BLOCKS = (NNODES * DIM + 255) / 256;          // 25000
    const int E_BLOCKS  = (ETOT + 255) / 256;                  // 3321
    const int EW_BLOCKS = (int)(((long long)ETOT * 32 + 255) / 256);  // 106250

    for (int l = 0; l < NLAYER; l++) {
        const float* in = (l == 0) ? x : hbuf;
        pack_w_kernel<<<(KDIM * DIM + 255) / 256, 256>>>(
            base_w + (size_t)l * DIM * DIM,
            spline_w + (size_t)l * DIM * DIM * NB,
            scaler + (size_t)l * DIM * DIM);
        feat_kernel<<<ND_BLOCKS, 256>>>(in);
        sgemm_kernel<<<(NNODES + 127) / 128, 256>>>();
        att_prep_kernel<<<(NNODES * 32 + 255) / 256, 256>>>(
            att_src + (size_t)l * DIM, att_dst + (size_t)l * DIM);
        init_layer_kernel<<<ND_BLOCKS, 256>>>(bias + (size_t)l * DIM);
        edge_a_kernel<<<E_BLOCKS, 256>>>(ei);
        edge_b_kernel<<<EW_BLOCKS, 256>>>(ei);
        silu_kernel<<<ND_BLOCKS, 256>>>();
    }
    zero_pooled_kernel<<<(NGR * DIM + 255) / 256, 256>>>();
    pool_kernel<<<(NNODES + 511) / 512, DIM>>>(batch);
    readout_kernel<<<NGR, DIM>>>(ro_bw, ro_sw, ro_sc, out);
}

// round 2
// speedup vs baseline: 1.2486x; 1.2486x over previous
#include <cuda_runtime.h>

#define NNODES 50000
#define NEDGE  800000
#define ETOT   850000
#define DIM    128
#define NH     4
#define NB     7
#define KDIM   1024   // DIM * (1 + NB), K ordered as k = j*8 + f (f=0: silu, f=1..7: bases)
#define NGR    64
#define NCLS   10
#define NLAYER 3

// ---------------- device scratch ----------------
__device__ __align__(16) float g_W[KDIM * DIM];              // packed per-layer weight (k-major)
__device__ __align__(16) float g_h[NNODES * DIM];            // layer input (post-silu)
__device__ __align__(16) float g_hl[NNODES * DIM];           // kan_linear output (split 0 -> combined)
__device__ __align__(16) float g_hl2[NNODES * DIM];          // kan_linear split-1 partial
__device__ __align__(16) float g_acc[NNODES * DIM];          // message accumulator
__device__ __align__(16) float g_asrc[NNODES * NH];
__device__ __align__(16) float g_adst[NNODES * NH];
__device__ __align__(16) float g_ex[(size_t)ETOT * NH];
__device__ __align__(16) float g_segsum[NNODES * NH];
__device__ __align__(16) float g_pooled[NGR * DIM];

// ---------------- helpers ----------------
__device__ __forceinline__ float silu_f(float x) {
    return x / (1.0f + __expf(-x));
}

// Cubic B-splines on uniform grid g[t] = 0.5*t - 2.5, t=0..10  (GS=4, K=3 -> 7 bases)
__device__ __forceinline__ void bsplines7(float x, float* out) {
    float b0[10];
#pragma unroll
    for (int i = 0; i < 10; i++) {
        float g0 = 0.5f * (float)i - 2.5f;
        b0[i] = (x >= g0 && x < g0 + 0.5f) ? 1.0f : 0.0f;
    }
    float b1[9];
#pragma unroll
    for (int i = 0; i < 9; i++) {
        float gi = 0.5f * (float)i - 2.5f;
        b1[i] = (x - gi) * 2.0f * b0[i] + ((gi + 1.0f) - x) * 2.0f * b0[i + 1];
    }
    float b2[8];
#pragma unroll
    for (int i = 0; i < 8; i++) {
        float gi = 0.5f * (float)i - 2.5f;
        b2[i] = (x - gi) * b1[i] + ((gi + 1.5f) - x) * b1[i + 1];
    }
#pragma unroll
    for (int i = 0; i < 7; i++) {
        float gi = 0.5f * (float)i - 2.5f;
        out[i] = ((x - gi) * b2[i] + ((gi + 2.0f) - x) * b2[i + 1]) * (1.0f / 1.5f);
    }
}

__device__ __forceinline__ void red_add_v4(float* addr, float4 v) {
    asm volatile("red.global.add.v4.f32 [%0], {%1, %2, %3, %4};"
                 :: "l"(addr), "f"(v.x), "f"(v.y), "f"(v.z), "f"(v.w) : "memory");
}

// ---------------- kernels ----------------

// Pack [1024 x 128] combined weight, K ordered k = j*8 + f
__global__ void pack_w_kernel(const float* __restrict__ bw,
                              const float* __restrict__ sw,
                              const float* __restrict__ sc) {
    int idx = blockIdx.x * blockDim.x + threadIdx.x;   // KDIM*DIM
    if (idx >= KDIM * DIM) return;
    int k = idx >> 7, o = idx & 127;
    int j = k >> 3, f = k & 7;
    float v;
    if (f == 0) v = bw[o * DIM + j];
    else        v = sw[(o * DIM + j) * NB + (f - 1)] * sc[o * DIM + j];
    g_W[idx] = v;
}

// Fused feature-build + SGEMM, split-K=2.
// grid (391, 2), block 256. Each block: M-tile 128, N=128, K-half 512 (=64 input cols).
__global__ void __launch_bounds__(256, 2) fkan_gemm_kernel(const float* __restrict__ in) {
    __shared__ float xs[64 * 128];   // xs[c_local][row]  (transposed x half-tile)
    __shared__ float As[16 * 128];   // As[kk][row]
    __shared__ float Bs[16 * 128];   // Bs[kk][col]

    int tid = threadIdx.x;
    int m0 = blockIdx.x * 128;
    int split = blockIdx.y;

    // Load x half-tile (rows m0..+127, cols split*64..+64), store transposed.
    {
        int r = tid >> 1;
        int cbase = (tid & 1) * 32;
        const float* src = in + (size_t)(m0 + r) * DIM + split * 64 + cbase;
        bool valid = (m0 + r) < NNODES;
#pragma unroll
        for (int q = 0; q < 8; q++) {
            float4 v = valid ? *(const float4*)(src + q * 4) : make_float4(0.f, 0.f, 0.f, 0.f);
            int c = cbase + q * 4;
            xs[(c + 0) * 128 + r] = v.x;
            xs[(c + 1) * 128 + r] = v.y;
            xs[(c + 2) * 128 + r] = v.z;
            xs[(c + 3) * 128 + r] = v.w;
        }
    }
    __syncthreads();

    float acc[8][8];
#pragma unroll
    for (int i = 0; i < 8; i++)
#pragma unroll
        for (int j = 0; j < 8; j++) acc[i][j] = 0.0f;

    int ty = tid >> 4, tx = tid & 15;
    int frow = tid & 127, dj = tid >> 7;       // feature stage: (row, local col pair)
    int br = tid >> 5, bc = (tid & 31) * 4;    // Bs load

    for (int k0 = 0; k0 < 512; k0 += 16) {
        // compute features for 2 input columns (j0, j0+1) of this chunk
        float xv = xs[((k0 >> 3) + dj) * 128 + frow];
        float fv[8];
        fv[0] = silu_f(xv);
        bsplines7(xv, fv + 1);
        // fetch W chunk (L2-resident, 512 KB total)
        int gk = split * 512 + k0;
        float4 b0 = *(const float4*)&g_W[(gk + br) * DIM + bc];
        float4 b1 = *(const float4*)&g_W[(gk + br + 8) * DIM + bc];
        __syncthreads();   // previous iter readers done
#pragma unroll
        for (int f = 0; f < 8; f++) As[(dj * 8 + f) * 128 + frow] = fv[f];
        *(float4*)&Bs[br * 128 + bc] = b0;
        *(float4*)&Bs[(br + 8) * 128 + bc] = b1;
        __syncthreads();
#pragma unroll
        for (int kk = 0; kk < 16; kk++) {
            float ra[8], rb[8];
            *(float4*)&ra[0] = *(const float4*)&As[kk * 128 + ty * 8];
            *(float4*)&ra[4] = *(const float4*)&As[kk * 128 + ty * 8 + 4];
            *(float4*)&rb[0] = *(const float4*)&Bs[kk * 128 + tx * 8];
            *(float4*)&rb[4] = *(const float4*)&Bs[kk * 128 + tx * 8 + 4];
#pragma unroll
            for (int i = 0; i < 8; i++)
#pragma unroll
                for (int j = 0; j < 8; j++)
                    acc[i][j] = fmaf(ra[i], rb[j], acc[i][j]);
        }
    }

    float* dst = split ? g_hl2 : g_hl;
#pragma unroll
    for (int i = 0; i < 8; i++) {
        int row = m0 + ty * 8 + i;
        if (row < NNODES) {
            *(float4*)&dst[(size_t)row * DIM + tx * 8] =
                make_float4(acc[i][0], acc[i][1], acc[i][2], acc[i][3]);
            *(float4*)&dst[(size_t)row * DIM + tx * 8 + 4] =
                make_float4(acc[i][4], acc[i][5], acc[i][6], acc[i][7]);
        }
    }
}

// Combine K-split partials into g_hl and compute attention dots. One warp per node.
__global__ void att_prep_kernel(const float* __restrict__ attS,
                                const float* __restrict__ attD) {
    int gid = blockIdx.x * blockDim.x + threadIdx.x;
    int n = gid >> 5, lane = gid & 31;
    if (n >= NNODES) return;
    size_t off = (size_t)n * DIM + lane * 4;
    float4 v0 = *(const float4*)&g_hl[off];
    float4 v1 = *(const float4*)&g_hl2[off];
    float4 v;
    v.x = v0.x + v1.x; v.y = v0.y + v1.y; v.z = v0.z + v1.z; v.w = v0.w + v1.w;
    *(float4*)&g_hl[off] = v;
    float4 ws = *(const float4*)&attS[lane * 4];
    float4 wd = *(const float4*)&attD[lane * 4];
    float ss = v.x * ws.x + v.y * ws.y + v.z * ws.z + v.w * ws.w;
    float sd = v.x * wd.x + v.y * wd.y + v.z * wd.z + v.w * wd.w;
#pragma unroll
    for (int o = 1; o <= 4; o <<= 1) {
        ss += __shfl_xor_sync(0xffffffffu, ss, o);
        sd += __shfl_xor_sync(0xffffffffu, sd, o);
    }
    if ((lane & 7) == 0) {
        int hh = lane >> 3;
        g_asrc[n * 4 + hh] = ss;
        g_adst[n * 4 + hh] = sd;
    }
}

// acc = bias (broadcast), segsum = 0
__global__ void init_layer_kernel(const float* __restrict__ bias) {
    int i = blockIdx.x * blockDim.x + threadIdx.x;
    if (i < NNODES * DIM) g_acc[i] = bias[i & 127];
    if (i < NNODES * NH) g_segsum[i] = 0.0f;
}

// Edge pass 1: ex = exp(leaky_relu(a_src[s]+a_dst[d])), segsum[d] += ex
__global__ void edge_a_kernel(const int* __restrict__ ei) {
    int e = blockIdx.x * blockDim.x + threadIdx.x;
    if (e >= ETOT) return;
    int s, d;
    if (e < NEDGE) { s = __ldg(&ei[e]); d = __ldg(&ei[NEDGE + e]); }
    else           { s = e - NEDGE; d = s; }
    float4 va = *(const float4*)&g_asrc[s * 4];
    float4 vb = *(const float4*)&g_adst[d * 4];
    float4 v;
    v.x = va.x + vb.x; v.y = va.y + vb.y; v.z = va.z + vb.z; v.w = va.w + vb.w;
    v.x = v.x > 0.f ? v.x : 0.2f * v.x;
    v.y = v.y > 0.f ? v.y : 0.2f * v.y;
    v.z = v.z > 0.f ? v.z : 0.2f * v.z;
    v.w = v.w > 0.f ? v.w : 0.2f * v.w;
    v.x = __expf(v.x); v.y = __expf(v.y); v.z = __expf(v.z); v.w = __expf(v.w);
    *(float4*)&g_ex[(size_t)e * 4] = v;
    red_add_v4(&g_segsum[d * 4], v);
}

// Edge pass 2: acc[d] += alpha * h[s]; one warp per edge
__global__ void edge_b_kernel(const int* __restrict__ ei) {
    int gid = blockIdx.x * blockDim.x + threadIdx.x;
    int e = gid >> 5;
    int lane = gid & 31;
    if (e >= ETOT) return;
    int s, d;
    if (e < NEDGE) { s = __ldg(&ei[e]); d = __ldg(&ei[NEDGE + e]); }
    else           { s = e - NEDGE; d = s; }
    int hh = lane >> 3;
    float alpha = g_ex[(size_t)e * 4 + hh] / (g_segsum[d * 4 + hh] + 1e-16f);
    float4 v = *(const float4*)&g_hl[(size_t)s * DIM + lane * 4];
    v.x *= alpha; v.y *= alpha; v.z *= alpha; v.w *= alpha;
    red_add_v4(&g_acc[(size_t)d * DIM + lane * 4], v);
}

__global__ void silu_kernel() {
    int i = blockIdx.x * blockDim.x + threadIdx.x;
    if (i < NNODES * DIM) {
        float v = g_acc[i];
        g_h[i] = silu_f(v);
    }
}

__global__ void zero_pooled_kernel() {
    int i = blockIdx.x * blockDim.x + threadIdx.x;
    if (i < NGR * DIM) g_pooled[i] = 0.0f;
}

// batch is sorted: running sum per column, flush on graph change
__global__ void pool_kernel(const int* __restrict__ batch) {
    int d0 = threadIdx.x;                 // 128 threads
    int r0 = blockIdx.x * 512;
    if (r0 >= NNODES) return;
    int rend = min(r0 + 512, NNODES);
    int cur = __ldg(&batch[r0]);
    float sum = 0.0f;
    for (int n = r0; n < rend; n++) {
        int g = __ldg(&batch[n]);
        if (g != cur) {
            atomicAdd(&g_pooled[cur * DIM + d0], sum);
            sum = 0.0f;
            cur = g;
        }
        sum += g_h[(size_t)n * DIM + d0];
    }
    atomicAdd(&g_pooled[cur * DIM + d0], sum);
}

// Readout KANLinear [128->10] + log_softmax. One block per graph, 128 threads.
__global__ void readout_kernel(const float* __restrict__ bw,
                               const float* __restrict__ sw,
                               const float* __restrict__ sc,
                               float* __restrict__ out) {
    __shared__ float feat[KDIM];
    __shared__ float sred[NCLS * 4];
    int g = blockIdx.x, t = threadIdx.x;
    float xv = g_pooled[g * DIM + t];
    feat[t] = xv / (1.0f + expf(-xv));
    float bs[7];
    bsplines7(xv, bs);
#pragma unroll
    for (int b = 0; b < 7; b++) feat[DIM + t * 7 + b] = bs[b];
    __syncthreads();

    float accv[NCLS];
#pragma unroll
    for (int o = 0; o < NCLS; o++) accv[o] = 0.0f;
#pragma unroll
    for (int kk = 0; kk < 8; kk++) {
        int k = kk * DIM + t;
        float f = feat[k];
        if (k < DIM) {
#pragma unroll
            for (int o = 0; o < NCLS; o++) accv[o] += f * bw[o * DIM + k];
        } else {
            int j = (k - DIM) / 7, b = (k - DIM) % 7;
#pragma unroll
            for (int o = 0; o < NCLS; o++)
                accv[o] += f * sw[o * DIM * NB + j * NB + b] * sc[o * DIM + j];
        }
    }
    int lane = t & 31, warp = t >> 5;
#pragma unroll
    for (int o = 0; o < NCLS; o++) {
        float v = accv[o];
#pragma unroll
        for (int off = 16; off >= 1; off >>= 1) v += __shfl_xor_sync(0xffffffffu, v, off);
        if (lane == 0) sred[o * 4 + warp] = v;
    }
    __syncthreads();
    if (t == 0) {
        float lg[NCLS];
        float mx = -1e30f;
#pragma unroll
        for (int o = 0; o < NCLS; o++) {
            lg[o] = sred[o * 4] + sred[o * 4 + 1] + sred[o * 4 + 2] + sred[o * 4 + 3];
            mx = fmaxf(mx, lg[o]);
        }
        float se = 0.0f;
#pragma unroll
        for (int o = 0; o < NCLS; o++) se += expf(lg[o] - mx);
        float lse = logf(se) + mx;
#pragma unroll
        for (int o = 0; o < NCLS; o++) out[g * NCLS + o] = lg[o] - lse;
    }
}

// ---------------- launch ----------------
extern "C" void kernel_launch(void* const* d_in, const int* in_sizes, int n_in,
                              void* d_out, int out_size) {
    const float* x        = (const float*)d_in[0];
    const int*   ei       = (const int*)d_in[1];
    const int*   batch    = (const int*)d_in[2];
    const float* base_w   = (const float*)d_in[3];
    const float* spline_w = (const float*)d_in[4];
    const float* scaler   = (const float*)d_in[5];
    const float* att_src  = (const float*)d_in[6];
    const float* att_dst  = (const float*)d_in[7];
    const float* bias     = (const float*)d_in[8];
    const float* ro_bw    = (const float*)d_in[9];
    const float* ro_sw    = (const float*)d_in[10];
    const float* ro_sc    = (const float*)d_in[11];
    float* out = (float*)d_out;

    float* hbuf = nullptr;
    cudaGetSymbolAddress((void**)&hbuf, g_h);

    const int ND_BLOCKS = (NNODES * DIM + 255) / 256;
    const int E_BLOCKS  = (ETOT + 255) / 256;
    const int EW_BLOCKS = (int)(((long long)ETOT * 32 + 255) / 256);

    for (int l = 0; l < NLAYER; l++) {
        const float* in = (l == 0) ? x : hbuf;
        pack_w_kernel<<<(KDIM * DIM + 255) / 256, 256>>>(
            base_w + (size_t)l * DIM * DIM,
            spline_w + (size_t)l * DIM * DIM * NB,
            scaler + (size_t)l * DIM * DIM);
        fkan_gemm_kernel<<<dim3((NNODES + 127) / 128, 2), 256>>>(in);
        att_prep_kernel<<<(NNODES * 32 + 255) / 256, 256>>>(
            att_src + (size_t)l * DIM, att_dst + (size_t)l * DIM);
        init_layer_kernel<<<ND_BLOCKS, 256>>>(bias + (size_t)l * DIM);
        edge_a_kernel<<<E_BLOCKS, 256>>>(ei);
        edge_b_kernel<<<EW_BLOCKS, 256>>>(ei);
        silu_kernel<<<ND_BLOCKS, 256>>>();
    }
    zero_pooled_kernel<<<(NGR * DIM + 255) / 256, 256>>>();
    pool_kernel<<<(NNODES + 511) / 512, DIM>>>(batch);
    readout_kernel<<<NGR, DIM>>>(ro_bw, ro_sw, ro_sc, out);
}

// round 4
// speedup vs baseline: 1.8208x; 1.4583x over previous
#include <cuda_runtime.h>
#include <cuda_bf16.h>
#include <cstdint>

#define NNODES 50000
#define NEDGE  800000
#define ETOT   850000
#define DIM    128
#define NH     4
#define NB     7
#define KDIM   1024
#define NGR    64
#define NCLS   10
#define NLAYER 3

#define MTILES ((NNODES + 127) / 128)   // 391

// ---------------- device scratch ----------------
__device__ __align__(16) __nv_bfloat16 g_Wh[KDIM * DIM];   // weight hi, [n][k] k-contiguous
__device__ __align__(16) __nv_bfloat16 g_Wl[KDIM * DIM];   // weight lo
__device__ __align__(16) float g_h[NNODES * DIM];
__device__ __align__(16) float g_hl[NNODES * DIM];
__device__ __align__(16) float g_acc[NNODES * DIM];
__device__ __align__(16) float g_asrc[NNODES * NH];
__device__ __align__(16) float g_adst[NNODES * NH];
__device__ __align__(16) float g_ex[(size_t)ETOT * NH];
__device__ __align__(16) float g_segsum[NNODES * NH];
__device__ __align__(16) float g_pooled[NGR * DIM];

// ---------------- helpers ----------------
__device__ __forceinline__ uint32_t smem_u32(const void* p) {
    uint32_t a;
    asm("{ .reg .u64 t; cvta.to.shared.u64 t, %1; cvt.u32.u64 %0, t; }" : "=r"(a) : "l"(p));
    return a;
}

// swizzle: chunk index (16B units) within 128B row, conflict-free for stores+ldmatrix
#define SWZ(c, row) (((c) ^ ((row) & 7) ^ (((row) >> 3) & 3)) & 7)

__device__ __forceinline__ void ldsm4(uint32_t a, uint32_t& r0, uint32_t& r1,
                                      uint32_t& r2, uint32_t& r3) {
    asm volatile("ldmatrix.sync.aligned.m8n8.x4.shared.b16 {%0,%1,%2,%3}, [%4];"
                 : "=r"(r0), "=r"(r1), "=r"(r2), "=r"(r3) : "r"(a));
}

__device__ __forceinline__ void mma16816(float* d, const uint32_t* a, const uint32_t* b) {
    asm volatile("mma.sync.aligned.m16n8k16.row.col.f32.bf16.bf16.f32 "
                 "{%0,%1,%2,%3}, {%4,%5,%6,%7}, {%8,%9}, {%0,%1,%2,%3};"
                 : "+f"(d[0]), "+f"(d[1]), "+f"(d[2]), "+f"(d[3])
                 : "r"(a[0]), "r"(a[1]), "r"(a[2]), "r"(a[3]), "r"(b[0]), "r"(b[1]));
}

__device__ __forceinline__ float silu_f(float x) { return x / (1.0f + __expf(-x)); }

__device__ __forceinline__ void bsplines7(float x, float* out) {
    float b0[10];
#pragma unroll
    for (int i = 0; i < 10; i++) {
        float g0 = 0.5f * (float)i - 2.5f;
        b0[i] = (x >= g0 && x < g0 + 0.5f) ? 1.0f : 0.0f;
    }
    float b1[9];
#pragma unroll
    for (int i = 0; i < 9; i++) {
        float gi = 0.5f * (float)i - 2.5f;
        b1[i] = (x - gi) * 2.0f * b0[i] + ((gi + 1.0f) - x) * 2.0f * b0[i + 1];
    }
    float b2[8];
#pragma unroll
    for (int i = 0; i < 8; i++) {
        float gi = 0.5f * (float)i - 2.5f;
        b2[i] = (x - gi) * b1[i] + ((gi + 1.5f) - x) * b1[i + 1];
    }
#pragma unroll
    for (int i = 0; i < 7; i++) {
        float gi = 0.5f * (float)i - 2.5f;
        out[i] = ((x - gi) * b2[i] + ((gi + 2.0f) - x) * b2[i + 1]) * (1.0f / 1.5f);
    }
}

// pack (a,b) to bf16x2 hi (low bits = a), residual to bf16x2 lo
__device__ __forceinline__ uint32_t pack_hilo(float a, float b, uint32_t& lo) {
    uint32_t hp;
    asm("cvt.rn.bf16x2.f32 %0, %1, %2;" : "=r"(hp) : "f"(b), "f"(a));
    float ha = __uint_as_float(hp << 16);
    float hb = __uint_as_float(hp & 0xFFFF0000u);
    float la = a - ha, lb = b - hb;
    asm("cvt.rn.bf16x2.f32 %0, %1, %2;" : "=r"(lo) : "f"(lb), "f"(la));
    return hp;
}

__device__ __forceinline__ void red_add_v4(float* addr, float4 v) {
    asm volatile("red.global.add.v4.f32 [%0], {%1, %2, %3, %4};"
                 :: "l"(addr), "f"(v.x), "f"(v.y), "f"(v.z), "f"(v.w) : "memory");
}

// ---------------- kernels ----------------

// Pack combined weight into bf16 hi/lo, layout [n=0..127][k=0..1023], k = j*8 + f
__global__ void pack_w_kernel(const float* __restrict__ bw,
                              const float* __restrict__ sw,
                              const float* __restrict__ sc) {
    int idx = blockIdx.x * blockDim.x + threadIdx.x;
    if (idx >= KDIM * DIM) return;
    int n = idx >> 10, k = idx & 1023;
    int j = k >> 3, f = k & 7;
    float v;
    if (f == 0) v = bw[n * DIM + j];
    else        v = sw[(n * DIM + j) * NB + (f - 1)] * sc[n * DIM + j];
    __nv_bfloat16 h = __float2bfloat16_rn(v);
    g_Wh[idx] = h;
    g_Wl[idx] = __float2bfloat16_rn(v - __bfloat162float(h));
}

// Fused feature-build + bf16 mma.sync GEMM (3-product hi/lo split) + att-dot epilogue.
// grid 391, block 256 (8 warps: warpM = wid&3 -> 32 rows, warpN = wid>>2 -> 64 cols).
// dyn smem 64KB: Ah[0,16K) Al[16K,32K) Bh[32K,48K) Bl[48K,64K); tiles 128 rows x 128B.
#define SMEM_BYTES 65536

__global__ void __launch_bounds__(256, 2) fkan_gemm_mma(const float* __restrict__ in,
                                                        const float* __restrict__ attS,
                                                        const float* __restrict__ attD) {
    extern __shared__ char dsm[];
    char* sAh = dsm;
    char* sAl = dsm + 16384;
    char* sBh = dsm + 32768;
    char* sBl = dsm + 49152;

    int tid = threadIdx.x;
    int wid = tid >> 5, lane = tid & 31;
    int m0 = blockIdx.x * 128;
    int warpM = wid & 3, warpN = wid >> 2;

    uint32_t uAh = smem_u32(sAh), uAl = smem_u32(sAl);
    uint32_t uBh = smem_u32(sBh), uBl = smem_u32(sBl);

    float acc[2][8][4];
#pragma unroll
    for (int f = 0; f < 2; f++)
#pragma unroll
        for (int j = 0; j < 8; j++)
#pragma unroll
            for (int q = 0; q < 4; q++) acc[f][j][q] = 0.0f;

    int rowb = tid & 127;               // build row (A) / weight row n (B)
    int cq = (tid >> 7) * 4;            // 16B-chunk quad base (0 or 4)
    bool rvalid = (m0 + rowb) < NNODES;

    int tg = lane >> 3, tr = lane & 7;  // ldmatrix address groups

    for (int cc = 0; cc < 16; cc++) {
        // ---- build A chunk (features) + load B chunk ----
        float4 xv4 = rvalid ? *(const float4*)(in + (size_t)(m0 + rowb) * DIM + cc * 8 + cq)
                            : make_float4(0.f, 0.f, 0.f, 0.f);
        const uint4* wsrc_h = (const uint4*)(g_Wh + rowb * KDIM + cc * 64 + cq * 8);
        const uint4* wsrc_l = (const uint4*)(g_Wl + rowb * KDIM + cc * 64 + cq * 8);
#pragma unroll
        for (int q = 0; q < 4; q++) {
            float xv = (q == 0) ? xv4.x : (q == 1) ? xv4.y : (q == 2) ? xv4.z : xv4.w;
            float fv[8];
            fv[0] = silu_f(xv);
            bsplines7(xv, fv + 1);
            uint4 uh, ul;
            uh.x = pack_hilo(fv[0], fv[1], ul.x);
            uh.y = pack_hilo(fv[2], fv[3], ul.y);
            uh.z = pack_hilo(fv[4], fv[5], ul.z);
            uh.w = pack_hilo(fv[6], fv[7], ul.w);
            int c = cq + q;
            uint32_t off = rowb * 128 + (SWZ(c, rowb) << 4);
            *(uint4*)(sAh + off) = uh;
            *(uint4*)(sAl + off) = ul;
            *(uint4*)(sBh + off) = wsrc_h[q];
            *(uint4*)(sBl + off) = wsrc_l[q];
        }
        __syncthreads();

        // ---- mma over 4 k-steps ----
#pragma unroll
        for (int ks = 0; ks < 4; ks++) {
            uint32_t ah[2][4], al[2][4];
#pragma unroll
            for (int f = 0; f < 2; f++) {
                int arow = warpM * 32 + f * 16 + (tg & 1) * 8 + tr;
                int acol = ks * 2 + (tg >> 1);
                uint32_t aoff = arow * 128 + (SWZ(acol, arow) << 4);
                ldsm4(uAh + aoff, ah[f][0], ah[f][1], ah[f][2], ah[f][3]);
                ldsm4(uAl + aoff, al[f][0], al[f][1], al[f][2], al[f][3]);
            }
#pragma unroll
            for (int gh = 0; gh < 2; gh++) {
                uint32_t bh[2][4], bl[2][4];
#pragma unroll
                for (int gg = 0; gg < 2; gg++) {
                    int g = gh * 2 + gg;
                    int brow = warpN * 64 + g * 16 + (tg >> 1) * 8 + tr;
                    int bcol = ks * 2 + (tg & 1);
                    uint32_t boff = brow * 128 + (SWZ(bcol, brow) << 4);
                    ldsm4(uBh + boff, bh[gg][0], bh[gg][1], bh[gg][2], bh[gg][3]);
                    ldsm4(uBl + boff, bl[gg][0], bl[gg][1], bl[gg][2], bl[gg][3]);
                }
#pragma unroll
                for (int f = 0; f < 2; f++)
#pragma unroll
                    for (int gg = 0; gg < 2; gg++) {
                        int g = gh * 2 + gg;
                        mma16816(acc[f][2 * g],     ah[f], &bh[gg][0]);
                        mma16816(acc[f][2 * g],     al[f], &bh[gg][0]);
                        mma16816(acc[f][2 * g],     ah[f], &bl[gg][0]);
                        mma16816(acc[f][2 * g + 1], ah[f], &bh[gg][2]);
                        mma16816(acc[f][2 * g + 1], al[f], &bh[gg][2]);
                        mma16816(acc[f][2 * g + 1], ah[f], &bl[gg][2]);
                    }
            }
        }
        __syncthreads();
    }

    // ---- epilogue: store h + fused attention dots ----
    int qd = lane >> 2, ql = lane & 3;
#pragma unroll
    for (int f = 0; f < 2; f++)
#pragma unroll
        for (int hh = 0; hh < 2; hh++) {
            int row = m0 + warpM * 32 + f * 16 + hh * 8 + qd;
            bool ok = row < NNODES;
            float ps0 = 0.f, pd0 = 0.f, ps1 = 0.f, pd1 = 0.f;
#pragma unroll
            for (int j = 0; j < 8; j++) {
                int col = warpN * 64 + j * 8 + ql * 2;
                float v0 = acc[f][j][hh * 2 + 0];
                float v1 = acc[f][j][hh * 2 + 1];
                if (ok) {
                    float2 st = make_float2(v0, v1);
                    *(float2*)&g_hl[(size_t)row * DIM + col] = st;
                }
                float s0 = __ldg(&attS[col]), s1 = __ldg(&attS[col + 1]);
                float d0 = __ldg(&attD[col]), d1 = __ldg(&attD[col + 1]);
                float ps = v0 * s0 + v1 * s1;
                float pd = v0 * d0 + v1 * d1;
                if (j < 4) { ps0 += ps; pd0 += pd; } else { ps1 += ps; pd1 += pd; }
            }
#pragma unroll
            for (int o = 1; o <= 2; o <<= 1) {
                ps0 += __shfl_xor_sync(0xffffffffu, ps0, o);
                pd0 += __shfl_xor_sync(0xffffffffu, pd0, o);
                ps1 += __shfl_xor_sync(0xffffffffu, ps1, o);
                pd1 += __shfl_xor_sync(0xffffffffu, pd1, o);
            }
            if (ql == 0 && ok) {
                int hbase = warpN * 2;
                g_asrc[row * 4 + hbase]     = ps0;
                g_asrc[row * 4 + hbase + 1] = ps1;
                g_adst[row * 4 + hbase]     = pd0;
                g_adst[row * 4 + hbase + 1] = pd1;
            }
        }
}

// Edge pass 1: ex = exp(leaky_relu(a_src[s]+a_dst[d])), segsum[d] += ex
__global__ void edge_a_kernel(const int* __restrict__ ei) {
    int e = blockIdx.x * blockDim.x + threadIdx.x;
    if (e >= ETOT) return;
    int s, d;
    if (e < NEDGE) { s = __ldg(&ei[e]); d = __ldg(&ei[NEDGE + e]); }
    else           { s = e - NEDGE; d = s; }
    float4 va = *(const float4*)&g_asrc[s * 4];
    float4 vb = *(const float4*)&g_adst[d * 4];
    float4 v;
    v.x = va.x + vb.x; v.y = va.y + vb.y; v.z = va.z + vb.z; v.w = va.w + vb.w;
    v.x = v.x > 0.f ? v.x : 0.2f * v.x;
    v.y = v.y > 0.f ? v.y : 0.2f * v.y;
    v.z = v.z > 0.f ? v.z : 0.2f * v.z;
    v.w = v.w > 0.f ? v.w : 0.2f * v.w;
    v.x = __expf(v.x); v.y = __expf(v.y); v.z = __expf(v.z); v.w = __expf(v.w);
    *(float4*)&g_ex[(size_t)e * 4] = v;
    red_add_v4(&g_segsum[d * 4], v);
}

// Edge pass 2: acc[d] += alpha * h[s]; one warp per edge
__global__ void edge_b_kernel(const int* __restrict__ ei) {
    int gid = blockIdx.x * blockDim.x + threadIdx.x;
    int e = gid >> 5;
    int lane = gid & 31;
    if (e >= ETOT) return;
    int s, d;
    if (e < NEDGE) { s = __ldg(&ei[e]); d = __ldg(&ei[NEDGE + e]); }
    else           { s = e - NEDGE; d = s; }
    int hh = lane >> 3;
    float alpha = g_ex[(size_t)e * 4 + hh] / (g_segsum[d * 4 + hh] + 1e-16f);
    float4 v = *(const float4*)&g_hl[(size_t)s * DIM + lane * 4];
    v.x *= alpha; v.y *= alpha; v.z *= alpha; v.w *= alpha;
    red_add_v4(&g_acc[(size_t)d * DIM + lane * 4], v);
}

// h = silu(acc + bias)
__global__ void silu_kernel(const float* __restrict__ bias) {
    int i = blockIdx.x * blockDim.x + threadIdx.x;
    if (i < NNODES * DIM) g_h[i] = silu_f(g_acc[i] + bias[i & 127]);
}

// batch sorted: running-sum pooling
__global__ void pool_kernel(const int* __restrict__ batch) {
    int d0 = threadIdx.x;
    int r0 = blockIdx.x * 512;
    if (r0 >= NNODES) return;
    int rend = min(r0 + 512, NNODES);
    int cur = __ldg(&batch[r0]);
    float sum = 0.0f;
    for (int n = r0; n < rend; n++) {
        int g = __ldg(&batch[n]);
        if (g != cur) {
            atomicAdd(&g_pooled[cur * DIM + d0], sum);
            sum = 0.0f;
            cur = g;
        }
        sum += g_h[(size_t)n * DIM + d0];
    }
    atomicAdd(&g_pooled[cur * DIM + d0], sum);
}

// Readout [128->10] + log_softmax
__global__ void readout_kernel(const float* __restrict__ bw,
                               const float* __restrict__ sw,
                               const float* __restrict__ sc,
                               float* __restrict__ out) {
    __shared__ float feat[KDIM];
    __shared__ float sred[NCLS * 4];
    int g = blockIdx.x, t = threadIdx.x;
    float xv = g_pooled[g * DIM + t];
    feat[t] = xv / (1.0f + expf(-xv));
    float bs[7];
    bsplines7(xv, bs);
#pragma unroll
    for (int b = 0; b < 7; b++) feat[DIM + t * 7 + b] = bs[b];
    __syncthreads();

    float accv[NCLS];
#pragma unroll
    for (int o = 0; o < NCLS; o++) accv[o] = 0.0f;
#pragma unroll
    for (int kk = 0; kk < 8; kk++) {
        int k = kk * DIM + t;
        float f = feat[k];
        if (k < DIM) {
#pragma unroll
            for (int o = 0; o < NCLS; o++) accv[o] += f * bw[o * DIM + k];
        } else {
            int j = (k - DIM) / 7, b = (k - DIM) % 7;
#pragma unroll
            for (int o = 0; o < NCLS; o++)
                accv[o] += f * sw[o * DIM * NB + j * NB + b] * sc[o * DIM + j];
        }
    }
    int lane = t & 31, warp = t >> 5;
#pragma unroll
    for (int o = 0; o < NCLS; o++) {
        float v = accv[o];
#pragma unroll
        for (int off = 16; off >= 1; off >>= 1) v += __shfl_xor_sync(0xffffffffu, v, off);
        if (lane == 0) sred[o * 4 + warp] = v;
    }
    __syncthreads();
    if (t == 0) {
        float lg[NCLS];
        float mx = -1e30f;
#pragma unroll
        for (int o = 0; o < NCLS; o++) {
            lg[o] = sred[o * 4] + sred[o * 4 + 1] + sred[o * 4 + 2] + sred[o * 4 + 3];
            mx = fmaxf(mx, lg[o]);
        }
        float se = 0.0f;
#pragma unroll
        for (int o = 0; o < NCLS; o++) se += expf(lg[o] - mx);
        float lse = logf(se) + mx;
#pragma unroll
        for (int o = 0; o < NCLS; o++) out[g * NCLS + o] = lg[o] - lse;
    }
}

// ---------------- launch ----------------
extern "C" void kernel_launch(void* const* d_in, const int* in_sizes, int n_in,
                              void* d_out, int out_size) {
    const float* x        = (const float*)d_in[0];
    const int*   ei       = (const int*)d_in[1];
    const int*   batch    = (const int*)d_in[2];
    const float* base_w   = (const float*)d_in[3];
    const float* spline_w = (const float*)d_in[4];
    const float* scaler   = (const float*)d_in[5];
    const float* att_src  = (const float*)d_in[6];
    const float* att_dst  = (const float*)d_in[7];
    const float* bias     = (const float*)d_in[8];
    const float* ro_bw    = (const float*)d_in[9];
    const float* ro_sw    = (const float*)d_in[10];
    const float* ro_sc    = (const float*)d_in[11];
    float* out = (float*)d_out;

    cudaFuncSetAttribute(fkan_gemm_mma, cudaFuncAttributeMaxDynamicSharedMemorySize, SMEM_BYTES);

    float *hbuf = nullptr, *accp = nullptr, *segp = nullptr, *poolp = nullptr;
    cudaGetSymbolAddress((void**)&hbuf, g_h);
    cudaGetSymbolAddress((void**)&accp, g_acc);
    cudaGetSymbolAddress((void**)&segp, g_segsum);
    cudaGetSymbolAddress((void**)&poolp, g_pooled);

    const int ND_BLOCKS = (NNODES * DIM + 255) / 256;
    const int E_BLOCKS  = (ETOT + 255) / 256;
    const int EW_BLOCKS = (int)(((long long)ETOT * 32 + 255) / 256);

    for (int l = 0; l < NLAYER; l++) {
        const float* in = (l == 0) ? x : hbuf;
        pack_w_kernel<<<(KDIM * DIM + 255) / 256, 256>>>(
            base_w + (size_t)l * DIM * DIM,
            spline_w + (size_t)l * DIM * DIM * NB,
            scaler + (size_t)l * DIM * DIM);
        cudaMemsetAsync(accp, 0, (size_t)NNODES * DIM * sizeof(float));
        cudaMemsetAsync(segp, 0, (size_t)NNODES * NH * sizeof(float));
        fkan_gemm_mma<<<MTILES, 256, SMEM_BYTES>>>(
            in, att_src + (size_t)l * DIM, att_dst + (size_t)l * DIM);
        edge_a_kernel<<<E_BLOCKS, 256>>>(ei);
        edge_b_kernel<<<EW_BLOCKS, 256>>>(ei);
        silu_kernel<<<ND_BLOCKS, 256>>>(bias + (size_t)l * DIM);
    }
    cudaMemsetAsync(poolp, 0, (size_t)NGR * DIM * sizeof(float));
    pool_kernel<<<(NNODES + 511) / 512, DIM>>>(batch);
    readout_kernel<<<NGR, DIM>>>(ro_bw, ro_sw, ro_sc, out);
}

// round 5
// speedup vs baseline: 2.4007x; 1.3185x over previous
#include <cuda_runtime.h>
#include <cuda_bf16.h>
#include <cstdint>

#define NNODES 50000
#define NEDGE  800000
#define ETOT   850000
#define DIM    128
#define NH     4
#define NB     7
#define KDIM   1024
#define NGR    64
#define NCLS   10
#define NLAYER 3

#define MTILES ((NNODES + 127) / 128)   // 391
#define SCAN_BLOCKS ((NNODES + 1023) / 1024)  // 49

// ---------------- device scratch ----------------
__device__ __align__(16) __nv_bfloat16 g_Wh[KDIM * DIM];
__device__ __align__(16) __nv_bfloat16 g_Wl[KDIM * DIM];
__device__ __align__(16) float g_h[NNODES * DIM];
__device__ __align__(16) float g_hl[NNODES * DIM];
__device__ __align__(16) float g_asrc[NNODES * NH];
__device__ __align__(16) float g_adst[NNODES * NH];
__device__ __align__(16) float g_pooled[NGR * DIM];
// CSR
__device__ int g_deg[NNODES];
__device__ int g_ptr[NNODES + 1];
__device__ int g_cur[NNODES];
__device__ int g_csrc[ETOT];
__device__ int g_bsum[SCAN_BLOCKS];
__device__ int g_boff[SCAN_BLOCKS];

// ---------------- helpers ----------------
__device__ __forceinline__ uint32_t smem_u32(const void* p) {
    uint32_t a;
    asm("{ .reg .u64 t; cvta.to.shared.u64 t, %1; cvt.u32.u64 %0, t; }" : "=r"(a) : "l"(p));
    return a;
}

#define SWZ(c, row) (((c) ^ ((row) & 7) ^ (((row) >> 3) & 3)) & 7)

__device__ __forceinline__ void ldsm4(uint32_t a, uint32_t& r0, uint32_t& r1,
                                      uint32_t& r2, uint32_t& r3) {
    asm volatile("ldmatrix.sync.aligned.m8n8.x4.shared.b16 {%0,%1,%2,%3}, [%4];"
                 : "=r"(r0), "=r"(r1), "=r"(r2), "=r"(r3) : "r"(a));
}

__device__ __forceinline__ void mma16816(float* d, const uint32_t* a, const uint32_t* b) {
    asm volatile("mma.sync.aligned.m16n8k16.row.col.f32.bf16.bf16.f32 "
                 "{%0,%1,%2,%3}, {%4,%5,%6,%7}, {%8,%9}, {%0,%1,%2,%3};"
                 : "+f"(d[0]), "+f"(d[1]), "+f"(d[2]), "+f"(d[3])
                 : "r"(a[0]), "r"(a[1]), "r"(a[2]), "r"(a[3]), "r"(b[0]), "r"(b[1]));
}

__device__ __forceinline__ float silu_f(float x) { return x / (1.0f + __expf(-x)); }

__device__ __forceinline__ void bsplines7(float x, float* out) {
    float b0[10];
#pragma unroll
    for (int i = 0; i < 10; i++) {
        float g0 = 0.5f * (float)i - 2.5f;
        b0[i] = (x >= g0 && x < g0 + 0.5f) ? 1.0f : 0.0f;
    }
    float b1[9];
#pragma unroll
    for (int i = 0; i < 9; i++) {
        float gi = 0.5f * (float)i - 2.5f;
        b1[i] = (x - gi) * 2.0f * b0[i] + ((gi + 1.0f) - x) * 2.0f * b0[i + 1];
    }
    float b2[8];
#pragma unroll
    for (int i = 0; i < 8; i++) {
        float gi = 0.5f * (float)i - 2.5f;
        b2[i] = (x - gi) * b1[i] + ((gi + 1.5f) - x) * b1[i + 1];
    }
#pragma unroll
    for (int i = 0; i < 7; i++) {
        float gi = 0.5f * (float)i - 2.5f;
        out[i] = ((x - gi) * b2[i] + ((gi + 2.0f) - x) * b2[i + 1]) * (1.0f / 1.5f);
    }
}

__device__ __forceinline__ uint32_t pack_hilo(float a, float b, uint32_t& lo) {
    uint32_t hp;
    asm("cvt.rn.bf16x2.f32 %0, %1, %2;" : "=r"(hp) : "f"(b), "f"(a));
    float ha = __uint_as_float(hp << 16);
    float hb = __uint_as_float(hp & 0xFFFF0000u);
    float la = a - ha, lb = b - hb;
    asm("cvt.rn.bf16x2.f32 %0, %1, %2;" : "=r"(lo) : "f"(lb), "f"(la));
    return hp;
}

// ---------------- CSR build ----------------
__global__ void deg_count_kernel(const int* __restrict__ ei) {
    int e = blockIdx.x * blockDim.x + threadIdx.x;
    if (e >= ETOT) return;
    int d = (e < NEDGE) ? __ldg(&ei[NEDGE + e]) : (e - NEDGE);
    atomicAdd(&g_deg[d], 1);
}

__global__ void scan1_kernel() {
    __shared__ int sh[1024];
    int t = threadIdx.x, b = blockIdx.x;
    int i = b * 1024 + t;
    int v = (i < NNODES) ? g_deg[i] : 0;
    sh[t] = v;
    __syncthreads();
#pragma unroll
    for (int off = 1; off < 1024; off <<= 1) {
        int add = (t >= off) ? sh[t - off] : 0;
        __syncthreads();
        sh[t] += add;
        __syncthreads();
    }
    if (i < NNODES) g_ptr[i] = sh[t] - v;
    if (t == 1023) g_bsum[b] = sh[t];
}

__global__ void scan2_kernel() {
    if (threadIdx.x == 0) {
        int run = 0;
        for (int b = 0; b < SCAN_BLOCKS; b++) { g_boff[b] = run; run += g_bsum[b]; }
        g_ptr[NNODES] = run;   // == ETOT
    }
}

__global__ void scan3_kernel() {
    int t = threadIdx.x, b = blockIdx.x;
    int i = b * 1024 + t;
    if (i < NNODES) {
        int p = g_ptr[i] + g_boff[b];
        g_ptr[i] = p;
        g_cur[i] = p;
    }
}

__global__ void scatter_kernel(const int* __restrict__ ei) {
    int e = blockIdx.x * blockDim.x + threadIdx.x;
    if (e >= ETOT) return;
    int s, d;
    if (e < NEDGE) { s = __ldg(&ei[e]); d = __ldg(&ei[NEDGE + e]); }
    else           { s = e - NEDGE; d = s; }
    int pos = atomicAdd(&g_cur[d], 1);
    g_csrc[pos] = s;
}

// ---------------- weight pack ----------------
__global__ void pack_w_kernel(const float* __restrict__ bw,
                              const float* __restrict__ sw,
                              const float* __restrict__ sc) {
    int idx = blockIdx.x * blockDim.x + threadIdx.x;
    if (idx >= KDIM * DIM) return;
    int n = idx >> 10, k = idx & 1023;
    int j = k >> 3, f = k & 7;
    float v;
    if (f == 0) v = bw[n * DIM + j];
    else        v = sw[(n * DIM + j) * NB + (f - 1)] * sc[n * DIM + j];
    __nv_bfloat16 h = __float2bfloat16_rn(v);
    g_Wh[idx] = h;
    g_Wl[idx] = __float2bfloat16_rn(v - __bfloat162float(h));
}

// ---------------- fused KAN-GEMM (bf16 mma.sync, 3-product split) ----------------
#define SMEM_BYTES 65536

__global__ void __launch_bounds__(256, 2) fkan_gemm_mma(const float* __restrict__ in,
                                                        const float* __restrict__ attS,
                                                        const float* __restrict__ attD) {
    extern __shared__ char dsm[];
    char* sAh = dsm;
    char* sAl = dsm + 16384;
    char* sBh = dsm + 32768;
    char* sBl = dsm + 49152;

    int tid = threadIdx.x;
    int wid = tid >> 5, lane = tid & 31;
    int m0 = blockIdx.x * 128;
    int warpM = wid & 3, warpN = wid >> 2;

    uint32_t uAh = smem_u32(sAh), uAl = smem_u32(sAl);
    uint32_t uBh = smem_u32(sBh), uBl = smem_u32(sBl);

    float acc[2][8][4];
#pragma unroll
    for (int f = 0; f < 2; f++)
#pragma unroll
        for (int j = 0; j < 8; j++)
#pragma unroll
            for (int q = 0; q < 4; q++) acc[f][j][q] = 0.0f;

    int rowb = tid & 127;
    int cq = (tid >> 7) * 4;
    bool rvalid = (m0 + rowb) < NNODES;
    int tg = lane >> 3, tr = lane & 7;

    for (int cc = 0; cc < 16; cc++) {
        float4 xv4 = rvalid ? *(const float4*)(in + (size_t)(m0 + rowb) * DIM + cc * 8 + cq)
                            : make_float4(0.f, 0.f, 0.f, 0.f);
        const uint4* wsrc_h = (const uint4*)(g_Wh + rowb * KDIM + cc * 64 + cq * 8);
        const uint4* wsrc_l = (const uint4*)(g_Wl + rowb * KDIM + cc * 64 + cq * 8);
#pragma unroll
        for (int q = 0; q < 4; q++) {
            float xv = (q == 0) ? xv4.x : (q == 1) ? xv4.y : (q == 2) ? xv4.z : xv4.w;
            float fv[8];
            fv[0] = silu_f(xv);
            bsplines7(xv, fv + 1);
            uint4 uh, ul;
            uh.x = pack_hilo(fv[0], fv[1], ul.x);
            uh.y = pack_hilo(fv[2], fv[3], ul.y);
            uh.z = pack_hilo(fv[4], fv[5], ul.z);
            uh.w = pack_hilo(fv[6], fv[7], ul.w);
            int c = cq + q;
            uint32_t off = rowb * 128 + (SWZ(c, rowb) << 4);
            *(uint4*)(sAh + off) = uh;
            *(uint4*)(sAl + off) = ul;
            *(uint4*)(sBh + off) = wsrc_h[q];
            *(uint4*)(sBl + off) = wsrc_l[q];
        }
        __syncthreads();

#pragma unroll
        for (int ks = 0; ks < 4; ks++) {
            uint32_t ah[2][4], al[2][4];
#pragma unroll
            for (int f = 0; f < 2; f++) {
                int arow = warpM * 32 + f * 16 + (tg & 1) * 8 + tr;
                int acol = ks * 2 + (tg >> 1);
                uint32_t aoff = arow * 128 + (SWZ(acol, arow) << 4);
                ldsm4(uAh + aoff, ah[f][0], ah[f][1], ah[f][2], ah[f][3]);
                ldsm4(uAl + aoff, al[f][0], al[f][1], al[f][2], al[f][3]);
            }
#pragma unroll
            for (int gh = 0; gh < 2; gh++) {
                uint32_t bh[2][4], bl[2][4];
#pragma unroll
                for (int gg = 0; gg < 2; gg++) {
                    int g = gh * 2 + gg;
                    int brow = warpN * 64 + g * 16 + (tg >> 1) * 8 + tr;
                    int bcol = ks * 2 + (tg & 1);
                    uint32_t boff = brow * 128 + (SWZ(bcol, brow) << 4);
                    ldsm4(uBh + boff, bh[gg][0], bh[gg][1], bh[gg][2], bh[gg][3]);
                    ldsm4(uBl + boff, bl[gg][0], bl[gg][1], bl[gg][2], bl[gg][3]);
                }
#pragma unroll
                for (int f = 0; f < 2; f++)
#pragma unroll
                    for (int gg = 0; gg < 2; gg++) {
                        int g = gh * 2 + gg;
                        mma16816(acc[f][2 * g],     ah[f], &bh[gg][0]);
                        mma16816(acc[f][2 * g],     al[f], &bh[gg][0]);
                        mma16816(acc[f][2 * g],     ah[f], &bl[gg][0]);
                        mma16816(acc[f][2 * g + 1], ah[f], &bh[gg][2]);
                        mma16816(acc[f][2 * g + 1], al[f], &bh[gg][2]);
                        mma16816(acc[f][2 * g + 1], ah[f], &bl[gg][2]);
                    }
            }
        }
        __syncthreads();
    }

    // epilogue: store h + fused attention dots
    int qd = lane >> 2, ql = lane & 3;
#pragma unroll
    for (int f = 0; f < 2; f++)
#pragma unroll
        for (int hh = 0; hh < 2; hh++) {
            int row = m0 + warpM * 32 + f * 16 + hh * 8 + qd;
            bool ok = row < NNODES;
            float ps0 = 0.f, pd0 = 0.f, ps1 = 0.f, pd1 = 0.f;
#pragma unroll
            for (int j = 0; j < 8; j++) {
                int col = warpN * 64 + j * 8 + ql * 2;
                float v0 = acc[f][j][hh * 2 + 0];
                float v1 = acc[f][j][hh * 2 + 1];
                if (ok) {
                    float2 st = make_float2(v0, v1);
                    *(float2*)&g_hl[(size_t)row * DIM + col] = st;
                }
                float s0 = __ldg(&attS[col]), s1 = __ldg(&attS[col + 1]);
                float d0 = __ldg(&attD[col]), d1 = __ldg(&attD[col + 1]);
                float ps = v0 * s0 + v1 * s1;
                float pd = v0 * d0 + v1 * d1;
                if (j < 4) { ps0 += ps; pd0 += pd; } else { ps1 += ps; pd1 += pd; }
            }
#pragma unroll
            for (int o = 1; o <= 2; o <<= 1) {
                ps0 += __shfl_xor_sync(0xffffffffu, ps0, o);
                pd0 += __shfl_xor_sync(0xffffffffu, pd0, o);
                ps1 += __shfl_xor_sync(0xffffffffu, ps1, o);
                pd1 += __shfl_xor_sync(0xffffffffu, pd1, o);
            }
            if (ql == 0 && ok) {
                int hbase = warpN * 2;
                g_asrc[row * 4 + hbase]     = ps0;
                g_asrc[row * 4 + hbase + 1] = ps1;
                g_adst[row * 4 + hbase]     = pd0;
                g_adst[row * 4 + hbase + 1] = pd1;
            }
        }
}

// ---------------- fused pull-mode edge phase ----------------
// One warp per dst node. acc = sum_e ex_e * h[src_e]; out = acc/sum_ex + bias; h = silu(out).
__global__ void __launch_bounds__(256) edge_fused_kernel(const float* __restrict__ bias) {
    int gid = blockIdx.x * blockDim.x + threadIdx.x;
    int n = gid >> 5, lane = gid & 31;
    if (n >= NNODES) return;
    int start = __ldg(&g_ptr[n]);
    int end   = __ldg(&g_ptr[n + 1]);
    int hh = lane >> 3;
    float bd = g_adst[n * 4 + hh];

    float4 acc = make_float4(0.f, 0.f, 0.f, 0.f);
    float sumex = 0.0f;

    for (int j0 = start; j0 < end; j0 += 32) {
        int m = min(32, end - j0);
        int s_pref = (j0 + lane < end) ? __ldg(&g_csrc[j0 + lane]) : 0;
#pragma unroll 4
        for (int i = 0; i < m; i++) {
            int s = __shfl_sync(0xffffffffu, s_pref, i);
            float a = __ldg(&g_asrc[s * 4 + hh]);
            float e = a + bd;
            e = (e > 0.f) ? e : 0.2f * e;
            float ex = __expf(e);
            sumex += ex;
            float4 v = *(const float4*)&g_hl[(size_t)s * DIM + lane * 4];
            acc.x = fmaf(ex, v.x, acc.x);
            acc.y = fmaf(ex, v.y, acc.y);
            acc.z = fmaf(ex, v.z, acc.z);
            acc.w = fmaf(ex, v.w, acc.w);
        }
    }
    float inv = 1.0f / (sumex + 1e-16f);
    float4 b4 = *(const float4*)&bias[lane * 4];
    float4 o;
    o.x = silu_f(acc.x * inv + b4.x);
    o.y = silu_f(acc.y * inv + b4.y);
    o.z = silu_f(acc.z * inv + b4.z);
    o.w = silu_f(acc.w * inv + b4.w);
    *(float4*)&g_h[(size_t)n * DIM + lane * 4] = o;
}

// ---------------- pooling + readout ----------------
__global__ void pool_kernel(const int* __restrict__ batch) {
    int d0 = threadIdx.x;
    int r0 = blockIdx.x * 512;
    if (r0 >= NNODES) return;
    int rend = min(r0 + 512, NNODES);
    int cur = __ldg(&batch[r0]);
    float sum = 0.0f;
    for (int n = r0; n < rend; n++) {
        int g = __ldg(&batch[n]);
        if (g != cur) {
            atomicAdd(&g_pooled[cur * DIM + d0], sum);
            sum = 0.0f;
            cur = g;
        }
        sum += g_h[(size_t)n * DIM + d0];
    }
    atomicAdd(&g_pooled[cur * DIM + d0], sum);
}

__global__ void readout_kernel(const float* __restrict__ bw,
                               const float* __restrict__ sw,
                               const float* __restrict__ sc,
                               float* __restrict__ out) {
    __shared__ float feat[KDIM];
    __shared__ float sred[NCLS * 4];
    int g = blockIdx.x, t = threadIdx.x;
    float xv = g_pooled[g * DIM + t];
    feat[t] = xv / (1.0f + expf(-xv));
    float bs[7];
    bsplines7(xv, bs);
#pragma unroll
    for (int b = 0; b < 7; b++) feat[DIM + t * 7 + b] = bs[b];
    __syncthreads();

    float accv[NCLS];
#pragma unroll
    for (int o = 0; o < NCLS; o++) accv[o] = 0.0f;
#pragma unroll
    for (int kk = 0; kk < 8; kk++) {
        int k = kk * DIM + t;
        float f = feat[k];
        if (k < DIM) {
#pragma unroll
            for (int o = 0; o < NCLS; o++) accv[o] += f * bw[o * DIM + k];
        } else {
            int j = (k - DIM) / 7, b = (k - DIM) % 7;
#pragma unroll
            for (int o = 0; o < NCLS; o++)
                accv[o] += f * sw[o * DIM * NB + j * NB + b] * sc[o * DIM + j];
        }
    }
    int lane = t & 31, warp = t >> 5;
#pragma unroll
    for (int o = 0; o < NCLS; o++) {
        float v = accv[o];
#pragma unroll
        for (int off = 16; off >= 1; off >>= 1) v += __shfl_xor_sync(0xffffffffu, v, off);
        if (lane == 0) sred[o * 4 + warp] = v;
    }
    __syncthreads();
    if (t == 0) {
        float lg[NCLS];
        float mx = -1e30f;
#pragma unroll
        for (int o = 0; o < NCLS; o++) {
            lg[o] = sred[o * 4] + sred[o * 4 + 1] + sred[o * 4 + 2] + sred[o * 4 + 3];
            mx = fmaxf(mx, lg[o]);
        }
        float se = 0.0f;
#pragma unroll
        for (int o = 0; o < NCLS; o++) se += expf(lg[o] - mx);
        float lse = logf(se) + mx;
#pragma unroll
        for (int o = 0; o < NCLS; o++) out[g * NCLS + o] = lg[o] - lse;
    }
}

// ---------------- launch ----------------
extern "C" void kernel_launch(void* const* d_in, const int* in_sizes, int n_in,
                              void* d_out, int out_size) {
    const float* x        = (const float*)d_in[0];
    const int*   ei       = (const int*)d_in[1];
    const int*   batch    = (const int*)d_in[2];
    const float* base_w   = (const float*)d_in[3];
    const float* spline_w = (const float*)d_in[4];
    const float* scaler   = (const float*)d_in[5];
    const float* att_src  = (const float*)d_in[6];
    const float* att_dst  = (const float*)d_in[7];
    const float* bias     = (const float*)d_in[8];
    const float* ro_bw    = (const float*)d_in[9];
    const float* ro_sw    = (const float*)d_in[10];
    const float* ro_sc    = (const float*)d_in[11];
    float* out = (float*)d_out;

    cudaFuncSetAttribute(fkan_gemm_mma, cudaFuncAttributeMaxDynamicSharedMemorySize, SMEM_BYTES);

    float *hbuf = nullptr, *poolp = nullptr;
    int* degp = nullptr;
    cudaGetSymbolAddress((void**)&hbuf, g_h);
    cudaGetSymbolAddress((void**)&poolp, g_pooled);
    cudaGetSymbolAddress((void**)&degp, g_deg);

    const int E_BLOCKS = (ETOT + 255) / 256;

    // ---- CSR build (once per run) ----
    cudaMemsetAsync(degp, 0, NNODES * sizeof(int));
    deg_count_kernel<<<E_BLOCKS, 256>>>(ei);
    scan1_kernel<<<SCAN_BLOCKS, 1024>>>();
    scan2_kernel<<<1, 32>>>();
    scan3_kernel<<<SCAN_BLOCKS, 1024>>>();
    scatter_kernel<<<E_BLOCKS, 256>>>(ei);

    for (int l = 0; l < NLAYER; l++) {
        const float* in = (l == 0) ? x : hbuf;
        pack_w_kernel<<<(KDIM * DIM + 255) / 256, 256>>>(
            base_w + (size_t)l * DIM * DIM,
            spline_w + (size_t)l * DIM * DIM * NB,
            scaler + (size_t)l * DIM * DIM);
        fkan_gemm_mma<<<MTILES, 256, SMEM_BYTES>>>(
            in, att_src + (size_t)l * DIM, att_dst + (size_t)l * DIM);
        edge_fused_kernel<<<(NNODES * 32 + 255) / 256, 256>>>(bias + (size_t)l * DIM);
    }
    cudaMemsetAsync(poolp, 0, (size_t)NGR * DIM * sizeof(float));
    pool_kernel<<<(NNODES + 511) / 512, DIM>>>(batch);
    readout_kernel<<<NGR, DIM>>>(ro_bw, ro_sw, ro_sc, out);
}